// round 4
// baseline (speedup 1.0000x reference)
#include <cuda_runtime.h>
#include <cuda_bf16.h>
#include <cstdint>
#include <math.h>

#define BB 16
#define HH 64
#define LL 16384
#define NN 32
#define DCC 128
#define CHLEN 256
#define NCH 64
#define HSTR 260

typedef unsigned long long ull;

__device__ __forceinline__ ull pk(float a, float b){ ull r; asm("mov.b64 %0, {%1,%2};" : "=l"(r) : "f"(a), "f"(b)); return r; }
__device__ __forceinline__ void upk(ull v, float& a, float& b){ asm("mov.b64 {%0,%1}, %2;" : "=f"(a), "=f"(b) : "l"(v)); }
__device__ __forceinline__ ull fma2(ull a, ull b, ull c){ ull d; asm("fma.rn.f32x2 %0, %1, %2, %3;" : "=l"(d) : "l"(a), "l"(b), "l"(c)); return d; }
__device__ __forceinline__ ull mul2(ull a, ull b){ ull d; asm("mul.rn.f32x2 %0, %1, %2;" : "=l"(d) : "l"(a), "l"(b)); return d; }

// ---------------- device scratch (no allocation) ----------------
__device__ float g_h[BB*HH*LL];   // h after mix1; reused for z after mix2
__device__ float g_y[BB*HH*LL];   // scan output
__device__ __align__(16) float g_lre[HH*NN];
__device__ __align__(16) float g_lim[HH*NN];
__device__ __align__(16) float g_c2re[HH*NN];
__device__ __align__(16) float g_c2imm[HH*NN];
__device__ __align__(16) float g_ltr[HH*NN];
__device__ __align__(16) float g_lti[HH*NN];
__device__ float g_gamma[BB*HH], g_beta[BB*HH];
__device__ double g_sum[HH], g_sq[HH];
__device__ float g_mean[HH], g_istd[HH];

// ============ K1: spectral constants (fp64) + zero stats ============
__global__ void k1_setup(const float* __restrict__ log_dt, const float* __restrict__ log_A_real,
                         const float* __restrict__ A_imag, const float* __restrict__ C_re,
                         const float* __restrict__ C_im){
  int idx = blockIdx.x * 256 + threadIdx.x;     // 8 blocks x 256 = 2048 = HH*NN
  if (blockIdx.x == 0 && threadIdx.x < HH){ g_sum[threadIdx.x] = 0.0; g_sq[threadIdx.x] = 0.0; }
  if (idx >= HH*NN) return;
  int h = idx >> 5;
  double dt = exp((double)log_dt[h]);
  double Ar = -exp((double)log_A_real[idx]);
  double Ai = (double)A_imag[idx];
  double dr = Ar*dt, di = Ai*dt;
  double er = exp(dr);
  double lr = er*cos(di), li = er*sin(di);
  g_lre[idx] = (float)lr; g_lim[idx] = (float)li;
  double eT = exp(dr*(double)CHLEN);
  g_ltr[idx] = (float)(eT*cos(di*(double)CHLEN));
  g_lti[idx] = (float)(eT*sin(di*(double)CHLEN));
  // Cd = (C_re + i C_im)*(lambda - 1)/A   (complex divide via conjugate)
  double nr = lr - 1.0, ni = li;
  double den = Ar*Ar + Ai*Ai;
  double fr = (nr*Ar + ni*Ai)/den;
  double fi = (ni*Ar - nr*Ai)/den;
  double cr = (double)C_re[idx], ci = (double)C_im[idx];
  double Cdr = cr*fr - ci*fi;
  double Cdi = cr*fi + ci*fr;
  g_c2re[idx]  = (float)( 2.0*Cdr);   // y contrib = c2re*s_re + c2imm*s_im
  g_c2imm[idx] = (float)(-2.0*Cdi);
}

// ============ K1b: FiLM  gb[b,j] = cond[b,:] . film_w[j,:] + film_b[j] ============
__global__ void k1b_film(const float* __restrict__ cond, const float* __restrict__ film_w,
                         const float* __restrict__ film_b){
  int idx = blockIdx.x * 256 + threadIdx.x;     // 8 blocks -> 2048 = BB*2H
  int b = idx >> 7, j = idx & 127;
  float s = film_b[j];
  const float* cp = cond + b*DCC;
  const float* wp = film_w + j*DCC;
  #pragma unroll 8
  for (int d = 0; d < DCC; d++) s = fmaf(cp[d], wp[d], s);
  if (j < HH) g_gamma[b*HH + j] = s; else g_beta[b*HH + (j - HH)] = s;
}

// ============ mix: out[b,g,l] = (prelu?)(W[g,:] . in[b,:,l] + bias[g]) ============
template<bool PRELU>
__global__ void __launch_bounds__(256) k_mix(const float* __restrict__ in, float* __restrict__ out,
                                             const float* __restrict__ W, const float* __restrict__ bias,
                                             const float* __restrict__ pa){
  __shared__ __align__(16) float Wt[64*68];     // Wt[h][g], padded row stride 68
  int tid = threadIdx.x;
  for (int i = tid; i < 4096; i += 256) Wt[(i & 63)*68 + (i >> 6)] = W[i];
  __syncthreads();
  int b = blockIdx.x >> 6;
  int l = ((blockIdx.x & 63) << 8) + tid;
  const float* ib = in + ((size_t)b*HH)*LL + l;
  ull acc[32];
  #pragma unroll
  for (int gp = 0; gp < 32; gp++) acc[gp] = pk(bias[2*gp], bias[2*gp+1]);
  #pragma unroll 4
  for (int hh = 0; hh < 64; hh++){
    float xv = ib[(size_t)hh*LL];
    ull h2 = pk(xv, xv);
    const ulonglong2* wp = (const ulonglong2*)(Wt + hh*68);
    #pragma unroll
    for (int g4 = 0; g4 < 16; g4++){
      ulonglong2 w = wp[g4];
      acc[2*g4]   = fma2(w.x, h2, acc[2*g4]);
      acc[2*g4+1] = fma2(w.y, h2, acc[2*g4+1]);
    }
  }
  float a = PRELU ? pa[0] : 0.f;
  float* ob = out + ((size_t)b*HH)*LL + l;
  #pragma unroll
  for (int gp = 0; gp < 32; gp++){
    float v0, v1; upk(acc[gp], v0, v1);
    if (PRELU){ v0 = v0 >= 0.f ? v0 : a*v0; v1 = v1 >= 0.f ? v1 : a*v1; }
    ob[(size_t)(2*gp)*LL]   = v0;
    ob[(size_t)(2*gp+1)*LL] = v1;
  }
}

// ============ K3: chunked S4D scan ============
// block = one (b,h). 64 chunks of 256 steps; each 4-lane group owns one chunk,
// each lane holds 8 modes as 4 packed f32x2 complex states.
__global__ void __launch_bounds__(256, 2) k3_scan(const float* __restrict__ dskip){
  extern __shared__ float sm[];
  float* hs  = sm;                 // NCH*HSTR
  float* esr = sm + NCH*HSTR;      // NCH*NN
  float* esi = esr + NCH*NN;       // NCH*NN
  int seq = blockIdx.x;            // b*64 + h
  int h = seq & 63;
  int tid = threadIdx.x;
  const float* hrow = g_h + (size_t)seq * LL;
  for (int i = tid*4; i < LL; i += 1024){
    float4 v = *(const float4*)(hrow + i);
    *(float4*)(hs + (i >> 8)*HSTR + (i & 255)) = v;
  }
  int lane = tid & 31, wrp = tid >> 5;
  int q = lane & 3;
  int chunk = wrp*8 + (lane >> 2);
  int nb = h*NN + q*8;
  ull lre[4], lim[4], limm[4], c2r[4], c2i[4];
  #pragma unroll
  for (int j = 0; j < 4; j++){
    float2 t;
    t = *(const float2*)(g_lre  + nb + 2*j); lre[j] = pk(t.x, t.y);
    t = *(const float2*)(g_lim  + nb + 2*j); lim[j] = pk(t.x, t.y); limm[j] = pk(-t.x, -t.y);
    t = *(const float2*)(g_c2re + nb + 2*j); c2r[j] = pk(t.x, t.y);
    t = *(const float2*)(g_c2imm+ nb + 2*j); c2i[j] = pk(t.x, t.y);
  }
  __syncthreads();

  // ---- phase 1: per-chunk end state from zero ----
  ull sre[4] = {0,0,0,0}, sim[4] = {0,0,0,0};
  const float* hp = hs + chunk*HSTR;
  #pragma unroll 4
  for (int t = 0; t < CHLEN; t++){
    float hv = hp[t];
    ull h2 = pk(hv, hv);
    #pragma unroll
    for (int j = 0; j < 4; j++){
      ull tim = mul2(lim[j], sre[j]);
      sre[j] = fma2(lre[j], sre[j], fma2(limm[j], sim[j], h2));
      sim[j] = fma2(lre[j], sim[j], tim);
    }
  }
  #pragma unroll
  for (int j = 0; j < 4; j++){
    float a0, a1;
    upk(sre[j], a0, a1); esr[chunk*NN + q*8 + 2*j] = a0; esr[chunk*NN + q*8 + 2*j + 1] = a1;
    upk(sim[j], a0, a1); esi[chunk*NN + q*8 + 2*j] = a0; esi[chunk*NN + q*8 + 2*j + 1] = a1;
  }
  __syncthreads();

  // ---- carry combine (warp 0, one lane per mode) ----
  if (wrp == 0){
    float ltr = g_ltr[h*NN + lane], lti = g_lti[h*NN + lane];
    float cr = 0.f, ci = 0.f;
    for (int c = 0; c < NCH; c++){
      float er = esr[c*NN + lane], ei = esi[c*NN + lane];
      esr[c*NN + lane] = cr; esi[c*NN + lane] = ci;
      float nr2 = fmaf(ltr, cr, fmaf(-lti, ci, er));
      float ni2 = fmaf(ltr, ci, fmaf( lti, cr, ei));
      cr = nr2; ci = ni2;
    }
  }
  __syncthreads();

  // ---- phase 2: rescan with carry init, emit y in-place ----
  #pragma unroll
  for (int j = 0; j < 4; j++){
    float2 t;
    t = *(const float2*)(esr + chunk*NN + q*8 + 2*j); sre[j] = pk(t.x, t.y);
    t = *(const float2*)(esi + chunk*NN + q*8 + 2*j); sim[j] = pk(t.x, t.y);
  }
  float ds = dskip[h];
  float* hw = hs + chunk*HSTR;
  bool writer = (q == 0);
  #pragma unroll 4
  for (int t = 0; t < CHLEN; t++){
    float hv = hw[t];
    ull h2 = pk(hv, hv);
    #pragma unroll
    for (int j = 0; j < 4; j++){
      ull tim = mul2(lim[j], sre[j]);
      sre[j] = fma2(lre[j], sre[j], fma2(limm[j], sim[j], h2));
      sim[j] = fma2(lre[j], sim[j], tim);
    }
    ull acc = mul2(c2r[0], sre[0]);
    acc = fma2(c2i[0], sim[0], acc);
    #pragma unroll
    for (int j = 1; j < 4; j++){
      acc = fma2(c2r[j], sre[j], acc);
      acc = fma2(c2i[j], sim[j], acc);
    }
    float a0, a1; upk(acc, a0, a1);
    float s = a0 + a1;
    s += __shfl_xor_sync(0xffffffffu, s, 1);
    s += __shfl_xor_sync(0xffffffffu, s, 2);
    if (writer) hw[t] = fmaf(ds, hv, s);
  }
  __syncthreads();
  float* yrow = g_y + (size_t)seq * LL;
  for (int i = tid*4; i < LL; i += 1024){
    float4 v = *(const float4*)(hs + (i >> 8)*HSTR + (i & 255));
    *(float4*)(yrow + i) = v;
  }
}

// ============ K4b: BN statistics over z (in g_h), per (b,g) block ============
__global__ void __launch_bounds__(256) k4b_stats(){
  int row = blockIdx.x;            // b*64 + g
  int g = row & 63;
  int tid = threadIdx.x;
  const float* zp = g_h + (size_t)row * LL;
  float s1 = 0.f, s2 = 0.f;
  #pragma unroll
  for (int it = 0; it < 16; it++){
    float4 v = *(const float4*)(zp + it*1024 + tid*4);   // stride = 256 threads * 4 floats
    s1 += v.x + v.y + v.z + v.w;
    s2 += v.x*v.x + v.y*v.y + v.z*v.z + v.w*v.w;
  }
  #pragma unroll
  for (int o = 16; o > 0; o >>= 1){
    s1 += __shfl_xor_sync(0xffffffffu, s1, o);
    s2 += __shfl_xor_sync(0xffffffffu, s2, o);
  }
  __shared__ float p1[8], p2[8];
  if ((tid & 31) == 0){ p1[tid >> 5] = s1; p2[tid >> 5] = s2; }
  __syncthreads();
  if (tid == 0){
    double a = 0.0, bq = 0.0;
    #pragma unroll
    for (int w = 0; w < 8; w++){ a += (double)p1[w]; bq += (double)p2[w]; }
    atomicAdd(&g_sum[g], a);
    atomicAdd(&g_sq[g], bq);
  }
}

__global__ void k5_final(){
  int g = threadIdx.x;
  if (g >= HH) return;
  double inv = 1.0 / ((double)BB * (double)LL);
  double m = g_sum[g] * inv;
  double v = g_sq[g] * inv - m*m;
  g_mean[g] = (float)m;
  g_istd[g] = (float)(1.0 / sqrt(v + 1e-5));
}

// ============ K6: normalize + FiLM + PReLU + depthwise residual ============
__global__ void __launch_bounds__(256) k6_out(const float* __restrict__ x, const float* __restrict__ res_w,
                                              const float* __restrict__ pa2, float* __restrict__ out){
  int bg = blockIdx.x >> 4;        // b*64 + g
  int g = bg & 63;
  int l = ((blockIdx.x & 15) << 10) + threadIdx.x*4;
  size_t off = (size_t)bg * LL + l;
  float mean = g_mean[g], istd = g_istd[g];
  float gm = g_gamma[(bg >> 6)*HH + g] * istd;
  float bt = g_beta[(bg >> 6)*HH + g];
  float sh = fmaf(-mean, gm, bt);  // y = z*gm + sh
  float a = pa2[0];
  float rw = res_w[g];
  float4 z = *(const float4*)(g_h + off);
  float4 xv = *(const float4*)(x + off);
  float4 r;
  float v;
  v = fmaf(z.x, gm, sh); v = v >= 0.f ? v : a*v; r.x = fmaf(rw, xv.x, v);
  v = fmaf(z.y, gm, sh); v = v >= 0.f ? v : a*v; r.y = fmaf(rw, xv.y, v);
  v = fmaf(z.z, gm, sh); v = v >= 0.f ? v : a*v; r.z = fmaf(rw, xv.z, v);
  v = fmaf(z.w, gm, sh); v = v >= 0.f ? v : a*v; r.w = fmaf(rw, xv.w, v);
  *(float4*)(out + off) = r;
}

// ============ launch ============
extern "C" void kernel_launch(void* const* d_in, const int* in_sizes, int n_in,
                              void* d_out, int out_size){
  const float* x        = (const float*)d_in[0];
  const float* cond     = (const float*)d_in[1];
  const float* linear_w = (const float*)d_in[2];
  const float* linear_b = (const float*)d_in[3];
  const float* prelu1_a = (const float*)d_in[4];
  const float* log_dt   = (const float*)d_in[5];
  const float* logAre   = (const float*)d_in[6];
  const float* A_imag   = (const float*)d_in[7];
  const float* C_re     = (const float*)d_in[8];
  const float* C_im     = (const float*)d_in[9];
  const float* Dskip    = (const float*)d_in[10];
  const float* out_w    = (const float*)d_in[11];
  const float* out_b    = (const float*)d_in[12];
  const float* film_w   = (const float*)d_in[13];
  const float* film_b   = (const float*)d_in[14];
  const float* prelu2_a = (const float*)d_in[15];
  const float* res_w    = (const float*)d_in[16];
  float* out = (float*)d_out;

  float* gh; cudaGetSymbolAddress((void**)&gh, g_h);
  float* gy; cudaGetSymbolAddress((void**)&gy, g_y);

  const int SMEM3 = (NCH*HSTR + 2*NCH*NN) * 4;   // 82944 bytes
  cudaFuncSetAttribute(k3_scan, cudaFuncAttributeMaxDynamicSharedMemorySize, SMEM3);

  k1_setup<<<8, 256>>>(log_dt, logAre, A_imag, C_re, C_im);
  k1b_film<<<8, 256>>>(cond, film_w, film_b);
  k_mix<true><<<1024, 256>>>(x, gh, linear_w, linear_b, prelu1_a);
  k3_scan<<<1024, 256, SMEM3>>>(Dskip);
  k_mix<false><<<1024, 256>>>(gy, gh, out_w, out_b, nullptr);
  k4b_stats<<<1024, 256>>>();
  k5_final<<<1, 64>>>();
  k6_out<<<16384, 256>>>(x, res_w, prelu2_a, out);
}

// round 15
// speedup vs baseline: 1.1356x; 1.1356x over previous
#include <cuda_runtime.h>
#include <cuda_bf16.h>
#include <cstdint>
#include <math.h>

#define BB 16
#define HH 64
#define LL 16384
#define NN 32
#define DCC 128
#define CHLEN 256
#define NCH 64
#define HSTR 260

typedef unsigned long long ull;

__device__ __forceinline__ ull pk(float a, float b){ ull r; asm("mov.b64 %0, {%1,%2};" : "=l"(r) : "f"(a), "f"(b)); return r; }
__device__ __forceinline__ void upk(ull v, float& a, float& b){ asm("mov.b64 {%0,%1}, %2;" : "=f"(a), "=f"(b) : "l"(v)); }
__device__ __forceinline__ ull fma2(ull a, ull b, ull c){ ull d; asm("fma.rn.f32x2 %0, %1, %2, %3;" : "=l"(d) : "l"(a), "l"(b), "l"(c)); return d; }
__device__ __forceinline__ ull mul2(ull a, ull b){ ull d; asm("mul.rn.f32x2 %0, %1, %2;" : "=l"(d) : "l"(a), "l"(b)); return d; }

// ---------------- device scratch (no allocation) ----------------
__device__ float g_h[BB*HH*LL];   // h after mix1; reused for z after mix2
__device__ float g_y[BB*HH*LL];   // scan output
__device__ __align__(16) float g_lre[HH*NN];
__device__ __align__(16) float g_lim[HH*NN];
__device__ __align__(16) float g_l2re[HH*NN];   // lambda^2
__device__ __align__(16) float g_l2im[HH*NN];
__device__ __align__(16) float g_c2re[HH*NN];
__device__ __align__(16) float g_c2imm[HH*NN];
__device__ __align__(16) float g_ltr[HH*NN];    // lambda^256
__device__ __align__(16) float g_lti[HH*NN];
__device__ float g_gamma[BB*HH], g_beta[BB*HH];
__device__ double g_sum[HH], g_sq[HH];
__device__ float g_mean[HH], g_istd[HH];

// ============ K1: spectral constants (fp64) + zero stats ============
__global__ void k1_setup(const float* __restrict__ log_dt, const float* __restrict__ log_A_real,
                         const float* __restrict__ A_imag, const float* __restrict__ C_re,
                         const float* __restrict__ C_im){
  int idx = blockIdx.x * 256 + threadIdx.x;     // 8 blocks x 256 = 2048 = HH*NN
  if (blockIdx.x == 0 && threadIdx.x < HH){ g_sum[threadIdx.x] = 0.0; g_sq[threadIdx.x] = 0.0; }
  if (idx >= HH*NN) return;
  int h = idx >> 5;
  double dt = exp((double)log_dt[h]);
  double Ar = -exp((double)log_A_real[idx]);
  double Ai = (double)A_imag[idx];
  double dr = Ar*dt, di = Ai*dt;
  double er = exp(dr);
  double lr = er*cos(di), li = er*sin(di);
  g_lre[idx] = (float)lr; g_lim[idx] = (float)li;
  double e2 = exp(2.0*dr);
  g_l2re[idx] = (float)(e2*cos(2.0*di));
  g_l2im[idx] = (float)(e2*sin(2.0*di));
  double eT = exp(dr*(double)CHLEN);
  g_ltr[idx] = (float)(eT*cos(di*(double)CHLEN));
  g_lti[idx] = (float)(eT*sin(di*(double)CHLEN));
  // Cd = (C_re + i C_im)*(lambda - 1)/A   (complex divide via conjugate)
  double nr = lr - 1.0, ni = li;
  double den = Ar*Ar + Ai*Ai;
  double fr = (nr*Ar + ni*Ai)/den;
  double fi = (ni*Ar - nr*Ai)/den;
  double cr = (double)C_re[idx], ci = (double)C_im[idx];
  double Cdr = cr*fr - ci*fi;
  double Cdi = cr*fi + ci*fr;
  g_c2re[idx]  = (float)( 2.0*Cdr);   // y contrib = c2re*s_re + c2imm*s_im
  g_c2imm[idx] = (float)(-2.0*Cdi);
}

// ============ K1b: FiLM ============
__global__ void k1b_film(const float* __restrict__ cond, const float* __restrict__ film_w,
                         const float* __restrict__ film_b){
  int idx = blockIdx.x * 256 + threadIdx.x;     // 8 blocks -> 2048 = BB*2H
  int b = idx >> 7, j = idx & 127;
  float s = film_b[j];
  const float* cp = cond + b*DCC;
  const float* wp = film_w + j*DCC;
  #pragma unroll 8
  for (int d = 0; d < DCC; d++) s = fmaf(cp[d], wp[d], s);
  if (j < HH) g_gamma[b*HH + j] = s; else g_beta[b*HH + (j - HH)] = s;
}

// ============ mix: out[b,g,l] = (prelu?)(W[g,:] . in[b,:,l] + bias[g]) ============
// Two channel-half passes with 16 packed accumulators each -> ~half the register
// pressure of the 32-acc version; input re-read hits L2 (input fits in 126MB L2).
template<bool PRELU>
__global__ void __launch_bounds__(256) k_mix(const float* __restrict__ in, float* __restrict__ out,
                                             const float* __restrict__ W, const float* __restrict__ bias,
                                             const float* __restrict__ pa){
  __shared__ __align__(16) float Wt[64*68];     // Wt[h][g], padded row stride 68
  int tid = threadIdx.x;
  for (int i = tid; i < 4096; i += 256) Wt[(i & 63)*68 + (i >> 6)] = W[i];
  __syncthreads();
  int b = blockIdx.x >> 6;
  int l = ((blockIdx.x & 63) << 8) + tid;
  const float* ib = in + ((size_t)b*HH)*LL + l;
  float* ob = out + ((size_t)b*HH)*LL + l;
  float a = PRELU ? pa[0] : 0.f;

  #pragma unroll 1
  for (int p = 0; p < 2; p++){
    int gb = p*32;
    ull acc[16];
    #pragma unroll
    for (int k = 0; k < 16; k++) acc[k] = pk(bias[gb + 2*k], bias[gb + 2*k + 1]);
    #pragma unroll 4
    for (int hh = 0; hh < 64; hh++){
      float xv = ib[(size_t)hh*LL];
      ull h2 = pk(xv, xv);
      const ulonglong2* wp = (const ulonglong2*)(Wt + hh*68 + gb);
      #pragma unroll
      for (int k4 = 0; k4 < 8; k4++){
        ulonglong2 w = wp[k4];
        acc[2*k4]   = fma2(w.x, h2, acc[2*k4]);
        acc[2*k4+1] = fma2(w.y, h2, acc[2*k4+1]);
      }
    }
    #pragma unroll
    for (int k = 0; k < 16; k++){
      float v0, v1; upk(acc[k], v0, v1);
      if (PRELU){ v0 = v0 >= 0.f ? v0 : a*v0; v1 = v1 >= 0.f ? v1 : a*v1; }
      ob[(size_t)(gb + 2*k)*LL]     = v0;
      ob[(size_t)(gb + 2*k + 1)*LL] = v1;
    }
  }
}

// ============ K3: chunked S4D scan, 512 threads ============
// block = one (b,h). 64 chunks x 256 steps; each 8-lane group owns one chunk,
// each lane holds 4 modes as 2 packed f32x2 complex states.
// Phase 1 uses 2-step lambda^2 jumping: s_{t+2} = l2*s_t + (l*h1 + h2).
__global__ void __launch_bounds__(512, 2) k3_scan(const float* __restrict__ dskip){
  extern __shared__ float sm[];
  float* hs  = sm;                 // NCH*HSTR
  float* esr = sm + NCH*HSTR;      // NCH*NN
  float* esi = esr + NCH*NN;       // NCH*NN
  int seq = blockIdx.x;            // b*64 + h
  int h = seq & 63;
  int tid = threadIdx.x;
  const float* hrow = g_h + (size_t)seq * LL;
  for (int i = tid*4; i < LL; i += 2048){
    float4 v = *(const float4*)(hrow + i);
    *(float4*)(hs + (i >> 8)*HSTR + (i & 255)) = v;
  }
  int lane = tid & 31, wrp = tid >> 5;
  int q = lane & 7;                    // lane within 8-lane chunk group
  int chunk = wrp*4 + (lane >> 3);     // 16 warps x 4 chunks = 64
  int nb = h*NN + q*4;                 // this lane's 4 modes

  // phase-1 coefficients: lambda (for u), lambda^2 (for jump)
  ull lre[2], lim[2], l2re[2], l2im[2], l2imm[2];
  #pragma unroll
  for (int j = 0; j < 2; j++){
    float2 t;
    t = *(const float2*)(g_lre  + nb + 2*j); lre[j]  = pk(t.x, t.y);
    t = *(const float2*)(g_lim  + nb + 2*j); lim[j]  = pk(t.x, t.y);
    t = *(const float2*)(g_l2re + nb + 2*j); l2re[j] = pk(t.x, t.y);
    t = *(const float2*)(g_l2im + nb + 2*j); l2im[j] = pk(t.x, t.y); l2imm[j] = pk(-t.x, -t.y);
  }
  __syncthreads();

  // ---- phase 1: per-chunk end state from zero, 2 steps per iteration ----
  ull sre[2] = {0,0}, sim[2] = {0,0};
  const float* hp = hs + chunk*HSTR;
  #pragma unroll 4
  for (int t = 0; t < CHLEN; t += 2){
    float2 hv = *(const float2*)(hp + t);
    ull h1 = pk(hv.x, hv.x), h2v = pk(hv.y, hv.y);
    #pragma unroll
    for (int j = 0; j < 2; j++){
      ull ure = fma2(lre[j], h1, h2v);                       // re(l*h1 + h2)
      ull tim = fma2(l2im[j], sre[j], mul2(lim[j], h1));     // l2im*sre + im(l*h1)
      sre[j] = fma2(l2re[j], sre[j], fma2(l2imm[j], sim[j], ure));
      sim[j] = fma2(l2re[j], sim[j], tim);
    }
  }
  #pragma unroll
  for (int j = 0; j < 2; j++){
    float a0, a1;
    upk(sre[j], a0, a1); esr[chunk*NN + q*4 + 2*j] = a0; esr[chunk*NN + q*4 + 2*j + 1] = a1;
    upk(sim[j], a0, a1); esi[chunk*NN + q*4 + 2*j] = a0; esi[chunk*NN + q*4 + 2*j + 1] = a1;
  }
  __syncthreads();

  // ---- carry combine (warp 0, one lane per mode) ----
  if (wrp == 0){
    float ltr = g_ltr[h*NN + lane], lti = g_lti[h*NN + lane];
    float cr = 0.f, ci = 0.f;
    for (int c = 0; c < NCH; c++){
      float er = esr[c*NN + lane], ei = esi[c*NN + lane];
      esr[c*NN + lane] = cr; esi[c*NN + lane] = ci;
      float nr2 = fmaf(ltr, cr, fmaf(-lti, ci, er));
      float ni2 = fmaf(ltr, ci, fmaf( lti, cr, ei));
      cr = nr2; ci = ni2;
    }
  }
  __syncthreads();

  // ---- phase 2: rescan with carry init, emit y in-place ----
  ull limm[2], c2r[2], c2i[2];
  #pragma unroll
  for (int j = 0; j < 2; j++){
    float2 t;
    t = *(const float2*)(g_lim  + nb + 2*j); limm[j] = pk(-t.x, -t.y);
    t = *(const float2*)(g_c2re + nb + 2*j); c2r[j]  = pk(t.x, t.y);
    t = *(const float2*)(g_c2imm+ nb + 2*j); c2i[j]  = pk(t.x, t.y);
    t = *(const float2*)(esr + chunk*NN + q*4 + 2*j); sre[j] = pk(t.x, t.y);
    t = *(const float2*)(esi + chunk*NN + q*4 + 2*j); sim[j] = pk(t.x, t.y);
  }
  float ds = dskip[h];
  float* hw = hs + chunk*HSTR;
  bool writer = (q == 0);
  #pragma unroll 4
  for (int t = 0; t < CHLEN; t++){
    float hv = hw[t];
    ull h2 = pk(hv, hv);
    #pragma unroll
    for (int j = 0; j < 2; j++){
      ull tim = mul2(lim[j], sre[j]);
      sre[j] = fma2(lre[j], sre[j], fma2(limm[j], sim[j], h2));
      sim[j] = fma2(lre[j], sim[j], tim);
    }
    ull acc = mul2(c2r[0], sre[0]);
    acc = fma2(c2i[0], sim[0], acc);
    acc = fma2(c2r[1], sre[1], acc);
    acc = fma2(c2i[1], sim[1], acc);
    float a0, a1; upk(acc, a0, a1);
    float s = a0 + a1;
    s += __shfl_xor_sync(0xffffffffu, s, 1);
    s += __shfl_xor_sync(0xffffffffu, s, 2);
    s += __shfl_xor_sync(0xffffffffu, s, 4);
    if (writer) hw[t] = fmaf(ds, hv, s);
  }
  __syncthreads();
  float* yrow = g_y + (size_t)seq * LL;
  for (int i = tid*4; i < LL; i += 2048){
    float4 v = *(const float4*)(hs + (i >> 8)*HSTR + (i & 255));
    *(float4*)(yrow + i) = v;
  }
}

// ============ K4b: BN statistics over z (in g_h) ============
__global__ void __launch_bounds__(256) k4b_stats(){
  int row = blockIdx.x;            // b*64 + g
  int g = row & 63;
  int tid = threadIdx.x;
  const float* zp = g_h + (size_t)row * LL;
  float s1 = 0.f, s2 = 0.f;
  #pragma unroll
  for (int it = 0; it < 16; it++){
    float4 v = *(const float4*)(zp + it*1024 + tid*4);
    s1 += v.x + v.y + v.z + v.w;
    s2 += v.x*v.x + v.y*v.y + v.z*v.z + v.w*v.w;
  }
  #pragma unroll
  for (int o = 16; o > 0; o >>= 1){
    s1 += __shfl_xor_sync(0xffffffffu, s1, o);
    s2 += __shfl_xor_sync(0xffffffffu, s2, o);
  }
  __shared__ float p1[8], p2[8];
  if ((tid & 31) == 0){ p1[tid >> 5] = s1; p2[tid >> 5] = s2; }
  __syncthreads();
  if (tid == 0){
    double a = 0.0, bq = 0.0;
    #pragma unroll
    for (int w = 0; w < 8; w++){ a += (double)p1[w]; bq += (double)p2[w]; }
    atomicAdd(&g_sum[g], a);
    atomicAdd(&g_sq[g], bq);
  }
}

__global__ void k5_final(){
  int g = threadIdx.x;
  if (g >= HH) return;
  double inv = 1.0 / ((double)BB * (double)LL);
  double m = g_sum[g] * inv;
  double v = g_sq[g] * inv - m*m;
  g_mean[g] = (float)m;
  g_istd[g] = (float)(1.0 / sqrt(v + 1e-5));
}

// ============ K6: normalize + FiLM + PReLU + depthwise residual ============
__global__ void __launch_bounds__(256) k6_out(const float* __restrict__ x, const float* __restrict__ res_w,
                                              const float* __restrict__ pa2, float* __restrict__ out){
  int bg = blockIdx.x >> 4;        // b*64 + g
  int g = bg & 63;
  int l = ((blockIdx.x & 15) << 10) + threadIdx.x*4;
  size_t off = (size_t)bg * LL + l;
  float mean = g_mean[g], istd = g_istd[g];
  float gm = g_gamma[(bg >> 6)*HH + g] * istd;
  float bt = g_beta[(bg >> 6)*HH + g];
  float sh = fmaf(-mean, gm, bt);  // y = z*gm + sh
  float a = pa2[0];
  float rw = res_w[g];
  float4 z = *(const float4*)(g_h + off);
  float4 xv = *(const float4*)(x + off);
  float4 r;
  float v;
  v = fmaf(z.x, gm, sh); v = v >= 0.f ? v : a*v; r.x = fmaf(rw, xv.x, v);
  v = fmaf(z.y, gm, sh); v = v >= 0.f ? v : a*v; r.y = fmaf(rw, xv.y, v);
  v = fmaf(z.z, gm, sh); v = v >= 0.f ? v : a*v; r.z = fmaf(rw, xv.z, v);
  v = fmaf(z.w, gm, sh); v = v >= 0.f ? v : a*v; r.w = fmaf(rw, xv.w, v);
  *(float4*)(out + off) = r;
}

// ============ launch ============
extern "C" void kernel_launch(void* const* d_in, const int* in_sizes, int n_in,
                              void* d_out, int out_size){
  const float* x        = (const float*)d_in[0];
  const float* cond     = (const float*)d_in[1];
  const float* linear_w = (const float*)d_in[2];
  const float* linear_b = (const float*)d_in[3];
  const float* prelu1_a = (const float*)d_in[4];
  const float* log_dt   = (const float*)d_in[5];
  const float* logAre   = (const float*)d_in[6];
  const float* A_imag   = (const float*)d_in[7];
  const float* C_re     = (const float*)d_in[8];
  const float* C_im     = (const float*)d_in[9];
  const float* Dskip    = (const float*)d_in[10];
  const float* out_w    = (const float*)d_in[11];
  const float* out_b    = (const float*)d_in[12];
  const float* film_w   = (const float*)d_in[13];
  const float* film_b   = (const float*)d_in[14];
  const float* prelu2_a = (const float*)d_in[15];
  const float* res_w    = (const float*)d_in[16];
  float* out = (float*)d_out;

  float* gh; cudaGetSymbolAddress((void**)&gh, g_h);
  float* gy; cudaGetSymbolAddress((void**)&gy, g_y);

  const int SMEM3 = (NCH*HSTR + 2*NCH*NN) * 4;   // 82944 bytes
  cudaFuncSetAttribute(k3_scan, cudaFuncAttributeMaxDynamicSharedMemorySize, SMEM3);

  k1_setup<<<8, 256>>>(log_dt, logAre, A_imag, C_re, C_im);
  k1b_film<<<8, 256>>>(cond, film_w, film_b);
  k_mix<true><<<1024, 256>>>(x, gh, linear_w, linear_b, prelu1_a);
  k3_scan<<<1024, 512, SMEM3>>>(Dskip);
  k_mix<false><<<1024, 256>>>(gy, gh, out_w, out_b, nullptr);
  k4b_stats<<<1024, 256>>>();
  k5_final<<<1, 64>>>();
  k6_out<<<16384, 256>>>(x, res_w, prelu2_a, out);
}